// round 7
// baseline (speedup 1.0000x reference)
#include <cuda_runtime.h>
#include <cuda_fp16.h>
#include <cstdint>

#define B_SZ 2
#define T_SZ 2048
#define C_SZ 2048
#define NH 16
#define NKV 4
#define HD 128
#define RMS_EPS 1.1920929e-07f
#define ATT_SCALE 0.08838834764831845f   // 1/sqrt(128)
#define NEG_BIG -1e30f

// ---------------- scratch (static device globals; no allocation) ----------------
__device__ __half g_xh[(size_t)B_SZ * T_SZ * C_SZ];             // x as half
__device__ __half g_wqh[(size_t)NH * HD * C_SZ];                // wq as half
__device__ __half g_wkh[(size_t)NKV * HD * C_SZ];               // wk as half
__device__ __half g_wvh[(size_t)NKV * HD * C_SZ];               // wv as half
__device__ __half g_wph[(size_t)C_SZ * C_SZ];                   // wproj as half
__device__ __half g_q[(size_t)B_SZ * T_SZ * NH * HD];           // q (rope+rms) half
__device__ __half g_k[(size_t)B_SZ * T_SZ * NKV * HD];          // k (rope+rms) half
__device__ __half g_vt[(size_t)B_SZ * NKV * HD * T_SZ];         // v transposed half
__device__ __half g_yh[(size_t)B_SZ * T_SZ * C_SZ];             // attn out half

// ---------------- helpers ----------------------------------------------------------
__device__ __forceinline__ uint32_t packh2(float lo, float hi) {
    __half2 h = __floats2half2_rn(lo, hi);
    return *(uint32_t*)&h;
}

__device__ __forceinline__ void mma_f16(float* c, const uint32_t* a, const uint32_t* b) {
    asm volatile("mma.sync.aligned.m16n8k16.row.col.f32.f16.f16.f32 "
                 "{%0,%1,%2,%3}, {%4,%5,%6,%7}, {%8,%9}, {%0,%1,%2,%3};"
                 : "+f"(c[0]), "+f"(c[1]), "+f"(c[2]), "+f"(c[3])
                 : "r"(a[0]), "r"(a[1]), "r"(a[2]), "r"(a[3]),
                   "r"(b[0]), "r"(b[1]));
}

#define CP_ASYNC16(dst_u32, src_ptr) \
    asm volatile("cp.async.cg.shared.global [%0], [%1], 16;" :: "r"(dst_u32), "l"(src_ptr))
#define CP_COMMIT() asm volatile("cp.async.commit_group;" ::: "memory")
#define CP_WAIT(n)  asm volatile("cp.async.wait_group %0;" :: "n"(n) : "memory")

__device__ __forceinline__ uint32_t smem_u32(const void* p) {
    return (uint32_t)__cvta_generic_to_shared(p);
}

// ---------------- fp32 -> half conversion -------------------------------------------
__global__ __launch_bounds__(256) void f2h_kernel(const float* __restrict__ in,
                                                  __half* __restrict__ out, int n4) {
    // n4 = n/4; each thread converts 4 floats per step
    for (int i = blockIdx.x * blockDim.x + threadIdx.x; i < n4; i += gridDim.x * blockDim.x) {
        float4 v = ((const float4*)in)[i];
        __half2 h0 = __floats2half2_rn(v.x, v.y);
        __half2 h1 = __floats2half2_rn(v.z, v.w);
        ((__half2*)out)[2 * i] = h0;
        ((__half2*)out)[2 * i + 1] = h1;
    }
}

// ---------------- all-half GEMM, cp.async pipelined: C = A[M,K] * B[N,K]^T ----------
// 128x128 CTA tile, K-chunk 64, 256 threads (8 warps 2x4), warp tile 64x32.
// MODE 0: fp32 C.  MODE 1: fused RoPE+RMSNorm, half C (N-tile == one head).
// MODE 2: half C transposed into g_vt [B][NKV][HD][T].
#define HLDW 36                     // uint32 words per smem row (64 halves + pad)
#define HTILEW (128 * HLDW)
#define SE_LD 130                   // MODE1 epilogue fp32 row stride

template <int MODE>
__global__ __launch_bounds__(256, 2) void gemm_h(const __half* __restrict__ A,
                                                 const __half* __restrict__ B,
                                                 void* __restrict__ Cv,
                                                 int M, int N, int K,
                                                 const float* __restrict__ cosb,
                                                 const float* __restrict__ sinb) {
    extern __shared__ uint32_t gsm[];
    uint32_t* As = gsm;                  // [2][128][36]
    uint32_t* Bs = gsm + 2 * HTILEW;     // [2][128][36]

    const int tid  = threadIdx.x;
    const int bm   = blockIdx.y * 128;
    const int bn   = blockIdx.x * 128;
    const int warp = tid >> 5;
    const int lane = tid & 31;
    const int wm   = warp >> 2;          // 0..1
    const int wn   = warp & 3;           // 0..3
    const int g    = lane >> 2;          // 0..7
    const int t    = lane & 3;           // 0..3

    float acc[4][4][4];
#pragma unroll
    for (int mi = 0; mi < 4; mi++)
#pragma unroll
        for (int ni = 0; ni < 4; ni++)
#pragma unroll
            for (int r = 0; r < 4; r++) acc[mi][ni][r] = 0.f;

    // staging mapping: row = tid>>1 (0..127), half-row = tid&1 (64B each)
    const int srow = tid >> 1;
    const int shalf = tid & 1;
    const __half* Ag = A + (size_t)(bm + srow) * K + shalf * 32;
    const __half* Bg = B + (size_t)(bn + srow) * K + shalf * 32;

    auto stage = [&](int buf, int kk) {
        uint32_t ad = smem_u32(As + buf * HTILEW + srow * HLDW + shalf * 16);
        uint32_t bd = smem_u32(Bs + buf * HTILEW + srow * HLDW + shalf * 16);
        const __half* asrc = Ag + kk;
        const __half* bsrc = Bg + kk;
#pragma unroll
        for (int i = 0; i < 4; i++) {
            CP_ASYNC16(ad + 16 * i, asrc + 8 * i);
            CP_ASYNC16(bd + 16 * i, bsrc + 8 * i);
        }
    };

    const int nchunk = K / 64;
    stage(0, 0);
    CP_COMMIT();

    for (int it = 0; it < nchunk; it++) {
        const int buf = it & 1;
        CP_WAIT(0);
        __syncthreads();
        if (it + 1 < nchunk) {
            stage(buf ^ 1, (it + 1) * 64);
            CP_COMMIT();
        }

        const uint32_t* as = As + buf * HTILEW;
        const uint32_t* bs = Bs + buf * HTILEW;
#pragma unroll
        for (int s16 = 0; s16 < 4; s16++) {
            const int kc = s16 * 8;
            uint32_t af[4][4], bf[4][2];
#pragma unroll
            for (int mi = 0; mi < 4; mi++) {
                const int r = wm * 64 + mi * 16 + g;
                af[mi][0] = as[r * HLDW + kc + t];
                af[mi][1] = as[(r + 8) * HLDW + kc + t];
                af[mi][2] = as[r * HLDW + kc + t + 4];
                af[mi][3] = as[(r + 8) * HLDW + kc + t + 4];
            }
#pragma unroll
            for (int ni = 0; ni < 4; ni++) {
                const int c = wn * 32 + ni * 8 + g;
                bf[ni][0] = bs[c * HLDW + kc + t];
                bf[ni][1] = bs[c * HLDW + kc + t + 4];
            }
#pragma unroll
            for (int mi = 0; mi < 4; mi++)
#pragma unroll
                for (int ni = 0; ni < 4; ni++)
                    mma_f16(acc[mi][ni], af[mi], bf[ni]);
        }
    }

    // ------------------- epilogues -------------------
    if constexpr (MODE == 0) {
        float* C = (float*)Cv;
#pragma unroll
        for (int mi = 0; mi < 4; mi++) {
            const int r = bm + wm * 64 + mi * 16 + g;
#pragma unroll
            for (int ni = 0; ni < 4; ni++) {
                const int c = bn + wn * 32 + ni * 8 + 2 * t;
                *(float2*)&C[(size_t)r * N + c] = make_float2(acc[mi][ni][0], acc[mi][ni][1]);
                *(float2*)&C[(size_t)(r + 8) * N + c] = make_float2(acc[mi][ni][2], acc[mi][ni][3]);
            }
        }
    } else if constexpr (MODE == 2) {
        __half* vt = (__half*)Cv;
        const int kvh = blockIdx.x;
#pragma unroll
        for (int mi = 0; mi < 4; mi++) {
            const int gr0 = bm + wm * 64 + mi * 16 + g;
            const int gr1 = gr0 + 8;
            const int b0v = gr0 >> 11, t0v = gr0 & (T_SZ - 1);
            const int b1v = gr1 >> 11, t1v = gr1 & (T_SZ - 1);
#pragma unroll
            for (int ni = 0; ni < 4; ni++) {
                const int d = wn * 32 + ni * 8 + 2 * t;
                size_t base0 = (((size_t)b0v * NKV + kvh) * HD + d) * T_SZ + t0v;
                size_t base1 = (((size_t)b1v * NKV + kvh) * HD + d) * T_SZ + t1v;
                vt[base0]        = __float2half_rn(acc[mi][ni][0]);
                vt[base0 + T_SZ] = __float2half_rn(acc[mi][ni][1]);
                vt[base1]        = __float2half_rn(acc[mi][ni][2]);
                vt[base1 + T_SZ] = __float2half_rn(acc[mi][ni][3]);
            }
        }
    } else {
        // MODE 1: fused RoPE + RMSNorm -> half (N-tile == one head of 128 dims)
        __syncthreads();
        float* sE = (float*)gsm;            // [128][130]
#pragma unroll
        for (int mi = 0; mi < 4; mi++) {
            const int r = wm * 64 + mi * 16 + g;
#pragma unroll
            for (int ni = 0; ni < 4; ni++) {
                const int c = wn * 32 + ni * 8 + 2 * t;
                *(float2*)&sE[r * SE_LD + c] = make_float2(acc[mi][ni][0], acc[mi][ni][1]);
                *(float2*)&sE[(r + 8) * SE_LD + c] = make_float2(acc[mi][ni][2], acc[mi][ni][3]);
            }
        }
        __syncthreads();

        __half* Ch = (__half*)Cv;
        const int row = tid >> 1;
        const int hf  = tid & 1;
        const int d0  = hf * 64;
        const int gr  = bm + row;
        const int tt  = gr & (T_SZ - 1);
        const float sgn = hf ? 1.f : -1.f;

        float rv[64];
        float ss = 0.f;
        const float* erow = sE + row * SE_LD;
        const float* cr = cosb + (size_t)tt * HD + d0;
        const float* sr = sinb + (size_t)tt * HD + d0;
#pragma unroll
        for (int i = 0; i < 64; i += 2) {
            float2 v = *(const float2*)&erow[d0 + i];
            float2 p = *(const float2*)&erow[(d0 ^ 64) + i];
            float2 c2 = *(const float2*)&cr[i];
            float2 s2 = *(const float2*)&sr[i];
            float r0 = v.x * c2.x + sgn * p.x * s2.x;
            float r1 = v.y * c2.y + sgn * p.y * s2.y;
            rv[i] = r0; rv[i + 1] = r1;
            ss += r0 * r0 + r1 * r1;
        }
        ss += __shfl_xor_sync(0xffffffffu, ss, 1);
        const float inv = rsqrtf(ss * (1.0f / HD) + RMS_EPS);

        __half2* dst = (__half2*)(Ch + (size_t)gr * N + blockIdx.x * 128 + d0);
#pragma unroll
        for (int i = 0; i < 64; i += 2) {
            dst[i >> 1] = __floats2half2_rn(rv[i] * inv, rv[i + 1] * inv);
        }
    }
}

// ---------------- flash attention (fp16 mma, cp.async double-buffered K/V) ----------
#define BM 128
#define BN 64
#define AK_LD 68    // words/row sK (64w data + pad): 272B, 16B-aligned
#define AV_LD 36    // words/row sVt (32w data + pad): 144B, 16B-aligned
#define AK_TILE (BN * AK_LD)
#define AV_TILE (HD * AV_LD)

__global__ __launch_bounds__(256, 1) void attn_f16(const __half* __restrict__ qb,
                                                   const __half* __restrict__ kb,
                                                   const __half* __restrict__ vtb,
                                                   __half* __restrict__ yb) {
    extern __shared__ uint32_t smu[];
    uint32_t* sK  = smu;                      // [2][64][68]
    uint32_t* sVt = smu + 2 * AK_TILE;        // [2][128][36]

    const int qt = gridDim.x - 1 - blockIdx.x;   // heavy tiles first
    const int h  = blockIdx.y;
    const int b  = blockIdx.z;
    const int kvh = h >> 2;
    const int qs = qt * BM;
    const int tid  = threadIdx.x;
    const int w    = tid >> 5;
    const int lane = tid & 31;
    const int g    = lane >> 2;
    const int t    = lane & 3;
    const int w16  = w * 16;

    // ---- Q fragments (half2 words straight from global) ----
    uint32_t qa[8][4];
    {
        const uint32_t* q0 = (const uint32_t*)(qb + (size_t)(b * T_SZ + qs + w16 + g) * (NH * HD) + h * HD);
        const uint32_t* q1 = q0 + 8 * (NH * HD / 2);
#pragma unroll
        for (int s16 = 0; s16 < 8; s16++) {
            qa[s16][0] = q0[s16 * 8 + t];
            qa[s16][1] = q1[s16 * 8 + t];
            qa[s16][2] = q0[s16 * 8 + t + 4];
            qa[s16][3] = q1[s16 * 8 + t + 4];
        }
    }

    float m0 = NEG_BIG, m1 = NEG_BIG, l0 = 0.f, l1 = 0.f;
    float o[16][4];
#pragma unroll
    for (int dt = 0; dt < 16; dt++)
#pragma unroll
        for (int r = 0; r < 4; r++) o[dt][r] = 0.f;

    const int row0 = qs + w16 + g;
    const int row1 = row0 + 8;

    // staging indices
    const int kr = tid >> 2, kq = tid & 3;        // K: row 0..63, quarter (64B)
    const int vr = tid >> 1, vh = tid & 1;        // Vt: row 0..127, half (64B)
    const __half* kbase = kb + (size_t)b * T_SZ * (NKV * HD) + kvh * HD;
    const __half* vbase = vtb + (((size_t)b * NKV + kvh) * HD + vr) * T_SZ;

    auto stage_kv = [&](int buf, int ks) {
        uint32_t kd = smem_u32(sK + buf * AK_TILE + kr * AK_LD + kq * 16);
        const __half* ksrc = kbase + (size_t)(ks + kr) * (NKV * HD) + kq * 32;
#pragma unroll
        for (int i = 0; i < 4; i++) CP_ASYNC16(kd + 16 * i, ksrc + 8 * i);
        uint32_t vd = smem_u32(sVt + buf * AV_TILE + vr * AV_LD + vh * 16);
        const __half* vsrc = vbase + ks + vh * 32;
#pragma unroll
        for (int i = 0; i < 4; i++) CP_ASYNC16(vd + 16 * i, vsrc + 8 * i);
    };

    const int ntile = (qs + BM) / BN;
    stage_kv(0, 0);
    CP_COMMIT();

    for (int it = 0; it < ntile; it++) {
        const int buf = it & 1;
        const int ks = it * BN;
        CP_WAIT(0);
        __syncthreads();
        if (it + 1 < ntile) {
            stage_kv(buf ^ 1, (it + 1) * BN);
            CP_COMMIT();
        }

        const int lim = qs + w16 + 15 - ks;     // max valid local col for this warp
        if (lim < 0) continue;                   // whole warp-tile masked
        const int ntmax = lim >= 63 ? 8 : ((lim >> 3) + 1);
        const int jmax  = lim >= 63 ? 4 : ((lim >> 4) + 1);

        const uint32_t* kt = sK + buf * AK_TILE;
        const uint32_t* vt = sVt + buf * AV_TILE;

        // ---- S = Q K^T ----
        float s[8][4];
#pragma unroll
        for (int nb = 0; nb < 8; nb++)
#pragma unroll
            for (int r = 0; r < 4; r++) s[nb][r] = 0.f;

#pragma unroll
        for (int s16 = 0; s16 < 8; s16++) {
#pragma unroll
            for (int nb = 0; nb < 8; nb++) {
                if (nb < ntmax) {
                    uint32_t bf[2];
                    bf[0] = kt[(nb * 8 + g) * AK_LD + s16 * 8 + t];
                    bf[1] = kt[(nb * 8 + g) * AK_LD + s16 * 8 + t + 4];
                    mma_f16(s[nb], qa[s16], bf);
                }
            }
        }

        // ---- online softmax ----
        const bool needs_mask = (ks + BN - 1) > (qs + w16);
        float rm0 = NEG_BIG, rm1 = NEG_BIG;
#pragma unroll
        for (int nb = 0; nb < 8; nb++) {
#pragma unroll
            for (int ci = 0; ci < 2; ci++) {
                const int col = ks + nb * 8 + 2 * t + ci;
                float v0 = s[nb][ci] * ATT_SCALE;
                float v1 = s[nb][2 + ci] * ATT_SCALE;
                if (needs_mask) {
                    if (col > row0) v0 = NEG_BIG;
                    if (col > row1) v1 = NEG_BIG;
                }
                s[nb][ci] = v0;
                s[nb][2 + ci] = v1;
                rm0 = fmaxf(rm0, v0);
                rm1 = fmaxf(rm1, v1);
            }
        }
        rm0 = fmaxf(rm0, __shfl_xor_sync(0xffffffffu, rm0, 1));
        rm0 = fmaxf(rm0, __shfl_xor_sync(0xffffffffu, rm0, 2));
        rm1 = fmaxf(rm1, __shfl_xor_sync(0xffffffffu, rm1, 1));
        rm1 = fmaxf(rm1, __shfl_xor_sync(0xffffffffu, rm1, 2));

        const float mn0 = fmaxf(m0, rm0);
        const float mn1 = fmaxf(m1, rm1);
        const float corr0 = __expf(m0 - mn0);
        const float corr1 = __expf(m1 - mn1);
        m0 = mn0; m1 = mn1;

        float rs0 = 0.f, rs1 = 0.f;
#pragma unroll
        for (int nb = 0; nb < 8; nb++) {
#pragma unroll
            for (int ci = 0; ci < 2; ci++) {
                float p0 = __expf(s[nb][ci] - mn0);
                float p1 = __expf(s[nb][2 + ci] - mn1);
                s[nb][ci] = p0;
                s[nb][2 + ci] = p1;
                rs0 += p0;
                rs1 += p1;
            }
        }
        rs0 += __shfl_xor_sync(0xffffffffu, rs0, 1);
        rs0 += __shfl_xor_sync(0xffffffffu, rs0, 2);
        rs1 += __shfl_xor_sync(0xffffffffu, rs1, 1);
        rs1 += __shfl_xor_sync(0xffffffffu, rs1, 2);

        l0 = l0 * corr0 + rs0;
        l1 = l1 * corr1 + rs1;

#pragma unroll
        for (int dt = 0; dt < 16; dt++) {
            o[dt][0] *= corr0; o[dt][1] *= corr0;
            o[dt][2] *= corr1; o[dt][3] *= corr1;
        }

        // ---- O += P V : accumulator -> half2 A-frags directly ----
#pragma unroll
        for (int j = 0; j < 4; j++) {
            if (j < jmax) {
                uint32_t pa[4];
                pa[0] = packh2(s[2 * j][0], s[2 * j][1]);
                pa[1] = packh2(s[2 * j][2], s[2 * j][3]);
                pa[2] = packh2(s[2 * j + 1][0], s[2 * j + 1][1]);
                pa[3] = packh2(s[2 * j + 1][2], s[2 * j + 1][3]);
#pragma unroll
                for (int dt = 0; dt < 16; dt++) {
                    uint32_t bf[2];
                    bf[0] = vt[(dt * 8 + g) * AV_LD + j * 8 + t];
                    bf[1] = vt[(dt * 8 + g) * AV_LD + j * 8 + t + 4];
                    mma_f16(o[dt], pa, bf);
                }
            }
        }
    }

    // ---- epilogue (half out) ----
    const float inv0 = 1.0f / l0;
    const float inv1 = 1.0f / l1;
    __half* dst0 = yb + (size_t)(b * T_SZ + row0) * C_SZ + h * HD;
    __half* dst1 = yb + (size_t)(b * T_SZ + row1) * C_SZ + h * HD;
#pragma unroll
    for (int dt = 0; dt < 16; dt++) {
        *(__half2*)(dst0 + dt * 8 + 2 * t) = __floats2half2_rn(o[dt][0] * inv0, o[dt][1] * inv0);
        *(__half2*)(dst1 + dt * 8 + 2 * t) = __floats2half2_rn(o[dt][2] * inv1, o[dt][3] * inv1);
    }
}

// ---------------- launch ---------------------------------------------------------
extern "C" void kernel_launch(void* const* d_in, const int* in_sizes, int n_in,
                              void* d_out, int out_size) {
    const float* x     = (const float*)d_in[0];
    const float* cosb  = (const float*)d_in[1];
    const float* sinb  = (const float*)d_in[2];
    const float* wq    = (const float*)d_in[3];
    const float* wk    = (const float*)d_in[4];
    const float* wv    = (const float*)d_in[5];
    const float* wproj = (const float*)d_in[6];
    float* out = (float*)d_out;

    __half *xh, *wqh, *wkh, *wvh, *wph, *qp, *kp, *vtp, *yh;
    cudaGetSymbolAddress((void**)&xh,  g_xh);
    cudaGetSymbolAddress((void**)&wqh, g_wqh);
    cudaGetSymbolAddress((void**)&wkh, g_wkh);
    cudaGetSymbolAddress((void**)&wvh, g_wvh);
    cudaGetSymbolAddress((void**)&wph, g_wph);
    cudaGetSymbolAddress((void**)&qp,  g_q);
    cudaGetSymbolAddress((void**)&kp,  g_k);
    cudaGetSymbolAddress((void**)&vtp, g_vt);
    cudaGetSymbolAddress((void**)&yh,  g_yh);

    const int M = B_SZ * T_SZ;   // 4096

    // fp32 -> half conversions
    f2h_kernel<<<512, 256>>>(x, xh, (M * C_SZ) / 4);
    f2h_kernel<<<256, 256>>>(wq, wqh, (NH * HD * C_SZ) / 4);
    f2h_kernel<<<128, 256>>>(wk, wkh, (NKV * HD * C_SZ) / 4);
    f2h_kernel<<<128, 256>>>(wv, wvh, (NKV * HD * C_SZ) / 4);
    f2h_kernel<<<256, 256>>>(wproj, wph, (C_SZ * C_SZ) / 4);

    const int gemm_smem = 4 * HTILEW * sizeof(uint32_t);   // 73728
    cudaFuncSetAttribute(gemm_h<0>, cudaFuncAttributeMaxDynamicSharedMemorySize, gemm_smem);
    cudaFuncSetAttribute(gemm_h<1>, cudaFuncAttributeMaxDynamicSharedMemorySize, gemm_smem);
    cudaFuncSetAttribute(gemm_h<2>, cudaFuncAttributeMaxDynamicSharedMemorySize, gemm_smem);

    // QKV projections: q/k fused RoPE+RMSNorm -> half; v -> transposed half
    gemm_h<1><<<dim3((NH * HD) / 128, M / 128), 256, gemm_smem>>>(
        xh, wqh, (void*)qp, M, NH * HD, C_SZ, cosb, sinb);
    gemm_h<1><<<dim3((NKV * HD) / 128, M / 128), 256, gemm_smem>>>(
        xh, wkh, (void*)kp, M, NKV * HD, C_SZ, cosb, sinb);
    gemm_h<2><<<dim3((NKV * HD) / 128, M / 128), 256, gemm_smem>>>(
        xh, wvh, (void*)vtp, M, NKV * HD, C_SZ, nullptr, nullptr);

    // attention (cp.async double-buffered K/V)
    const int attn_smem = (2 * AK_TILE + 2 * AV_TILE) * sizeof(uint32_t);  // 71680
    cudaFuncSetAttribute(attn_f16, cudaFuncAttributeMaxDynamicSharedMemorySize, attn_smem);
    attn_f16<<<dim3(T_SZ / BM, NH, B_SZ), 256, attn_smem>>>(qp, kp, vtp, yh);

    // output projection (half inputs, fp32 out)
    gemm_h<0><<<dim3(C_SZ / 128, M / 128), 256, gemm_smem>>>(
        yh, wph, (void*)out, M, C_SZ, C_SZ, nullptr, nullptr);
}

// round 8
// speedup vs baseline: 1.1163x; 1.1163x over previous
#include <cuda_runtime.h>
#include <cuda_fp16.h>
#include <cstdint>

#define B_SZ 2
#define T_SZ 2048
#define C_SZ 2048
#define NH 16
#define NKV 4
#define HD 128
#define RMS_EPS 1.1920929e-07f
#define ATT_SCALE 0.08838834764831845f   // 1/sqrt(128)
#define NEG_BIG -1e30f

// ---------------- scratch (static device globals; no allocation) ----------------
__device__ __half g_q[(size_t)B_SZ * T_SZ * NH * HD];           // q (rope+rms) half
__device__ __half g_k[(size_t)B_SZ * T_SZ * NKV * HD];          // k (rope+rms) half
__device__ __half g_vt[(size_t)B_SZ * NKV * HD * T_SZ];         // v transposed half
__device__ float  g_y[(size_t)B_SZ * T_SZ * C_SZ];              // attn out fp32

// ---------------- helpers ----------------------------------------------------------
__device__ __forceinline__ uint32_t packh2(float lo, float hi) {
    __half2 h = __floats2half2_rn(lo, hi);
    return *(uint32_t*)&h;
}

__device__ __forceinline__ void mma_f16(float* c, const uint32_t* a, const uint32_t* b) {
    asm volatile("mma.sync.aligned.m16n8k16.row.col.f32.f16.f16.f32 "
                 "{%0,%1,%2,%3}, {%4,%5,%6,%7}, {%8,%9}, {%0,%1,%2,%3};"
                 : "+f"(c[0]), "+f"(c[1]), "+f"(c[2]), "+f"(c[3])
                 : "r"(a[0]), "r"(a[1]), "r"(a[2]), "r"(a[3]),
                   "r"(b[0]), "r"(b[1]));
}

__device__ __forceinline__ void ldsm_x4(uint32_t* r, uint32_t saddr) {
    asm volatile("ldmatrix.sync.aligned.m8n8.x4.shared.b16 {%0,%1,%2,%3}, [%4];"
                 : "=r"(r[0]), "=r"(r[1]), "=r"(r[2]), "=r"(r[3]) : "r"(saddr));
}
__device__ __forceinline__ void ldsm_x2(uint32_t* r, uint32_t saddr) {
    asm volatile("ldmatrix.sync.aligned.m8n8.x2.shared.b16 {%0,%1}, [%2];"
                 : "=r"(r[0]), "=r"(r[1]) : "r"(saddr));
}

#define CP_ASYNC16(dst_u32, src_ptr) \
    asm volatile("cp.async.cg.shared.global [%0], [%1], 16;" :: "r"(dst_u32), "l"(src_ptr))
#define CP_COMMIT() asm volatile("cp.async.commit_group;" ::: "memory")
#define CP_WAIT(n)  asm volatile("cp.async.wait_group %0;" :: "n"(n) : "memory")

__device__ __forceinline__ uint32_t smem_u32(const void* p) {
    return (uint32_t)__cvta_generic_to_shared(p);
}

// ---------------- FP16 GEMM: C[M,N] = A[M,K] * B[N,K]^T ---------------------------
// 128x128 CTA tile, K-chunk 32, 256 threads (8 warps 2x4), warp tile 64x32.
// fp32 global inputs -> half smem at staging (once/elem), register prefetch,
// double-buffered smem, ldmatrix fragment loads.
// MODE 0: fp32 C.  MODE 1: fused RoPE+RMSNorm half C.  MODE 2: half C -> g_vt^T.
#define GLDW 20                     // words/row: 16 data + 4 pad (banks 20g+t distinct)
#define GTILEW (128 * GLDW)
#define SE_LD 130

template <int MODE>
__global__ __launch_bounds__(256, 2) void gemm_f16(const float* __restrict__ A,
                                                   const float* __restrict__ B,
                                                   void* __restrict__ Cv,
                                                   int M, int N, int K,
                                                   const float* __restrict__ cosb,
                                                   const float* __restrict__ sinb) {
    extern __shared__ uint32_t gsm[];
    uint32_t* As = gsm;                  // [2][128][20]
    uint32_t* Bs = gsm + 2 * GTILEW;     // [2][128][20]
    const uint32_t aS = smem_u32(As);
    const uint32_t bS = smem_u32(Bs);

    const int tid  = threadIdx.x;
    const int bm   = blockIdx.y * 128;
    const int bn   = blockIdx.x * 128;
    const int warp = tid >> 5;
    const int lane = tid & 31;
    const int wm   = warp >> 2;          // 0..1
    const int wn   = warp & 3;           // 0..3
    const int g    = lane >> 2;          // 0..7
    const int t    = lane & 3;           // 0..3
    const int arow = tid >> 3;           // 0..31
    const int ac4  = (tid & 7) * 4;      // fp32 col base
    const int wix  = ac4 >> 1;           // word index

    // ldmatrix lane terms
    const int lrow16 = lane & 15;
    const int lcolA  = (lane >> 4) * 4;
    const int lrow8  = lane & 7;
    const int lcolB  = ((lane >> 3) & 1) * 4;

    float acc[4][4][4];
#pragma unroll
    for (int mi = 0; mi < 4; mi++)
#pragma unroll
        for (int ni = 0; ni < 4; ni++)
#pragma unroll
            for (int r = 0; r < 4; r++) acc[mi][ni][r] = 0.f;

    const float* Ag = A + (size_t)(bm + arow) * K + ac4;
    const float* Bg = B + (size_t)(bn + arow) * K + ac4;

    float4 ra[4], rb[4];
#pragma unroll
    for (int p = 0; p < 4; p++) {
        ra[p] = *(const float4*)(Ag + (size_t)p * 32 * K);
        rb[p] = *(const float4*)(Bg + (size_t)p * 32 * K);
    }

    auto sts_tile = [&](int buf) {
        uint32_t* ad = As + buf * GTILEW;
        uint32_t* bd = Bs + buf * GTILEW;
#pragma unroll
        for (int p = 0; p < 4; p++) {
            uint2 a2 = make_uint2(packh2(ra[p].x, ra[p].y), packh2(ra[p].z, ra[p].w));
            uint2 b2 = make_uint2(packh2(rb[p].x, rb[p].y), packh2(rb[p].z, rb[p].w));
            *(uint2*)&ad[(arow + 32 * p) * GLDW + wix] = a2;
            *(uint2*)&bd[(arow + 32 * p) * GLDW + wix] = b2;
        }
    };

    const int nchunk = K / 32;
    sts_tile(0);
    __syncthreads();

    for (int it = 0; it < nchunk; it++) {
        const int buf = it & 1;
        const bool more = (it + 1 < nchunk);
        if (more) {
            const int kk = (it + 1) * 32;
#pragma unroll
            for (int p = 0; p < 4; p++) {
                ra[p] = *(const float4*)(Ag + (size_t)p * 32 * K + kk);
                rb[p] = *(const float4*)(Bg + (size_t)p * 32 * K + kk);
            }
        }

        const uint32_t abase = aS + 4 * (buf * GTILEW);
        const uint32_t bbase = bS + 4 * (buf * GTILEW);
#pragma unroll
        for (int s16 = 0; s16 < 2; s16++) {
            const int kc = s16 * 8;
            uint32_t af[4][4], bf[4][2];
#pragma unroll
            for (int mi = 0; mi < 4; mi++)
                ldsm_x4(af[mi], abase + 4 * ((wm * 64 + mi * 16 + lrow16) * GLDW + kc + lcolA));
#pragma unroll
            for (int ni = 0; ni < 4; ni++)
                ldsm_x2(bf[ni], bbase + 4 * ((wn * 32 + ni * 8 + lrow8) * GLDW + kc + lcolB));
#pragma unroll
            for (int mi = 0; mi < 4; mi++)
#pragma unroll
                for (int ni = 0; ni < 4; ni++)
                    mma_f16(acc[mi][ni], af[mi], bf[ni]);
        }

        if (more) {
            sts_tile(buf ^ 1);
            __syncthreads();
        }
    }

    // ------------------- epilogues -------------------
    if constexpr (MODE == 0) {
        float* C = (float*)Cv;
#pragma unroll
        for (int mi = 0; mi < 4; mi++) {
            const int r = bm + wm * 64 + mi * 16 + g;
#pragma unroll
            for (int ni = 0; ni < 4; ni++) {
                const int c = bn + wn * 32 + ni * 8 + 2 * t;
                *(float2*)&C[(size_t)r * N + c] = make_float2(acc[mi][ni][0], acc[mi][ni][1]);
                *(float2*)&C[(size_t)(r + 8) * N + c] = make_float2(acc[mi][ni][2], acc[mi][ni][3]);
            }
        }
    } else if constexpr (MODE == 2) {
        __half* vt = (__half*)Cv;
        const int kvh = blockIdx.x;
#pragma unroll
        for (int mi = 0; mi < 4; mi++) {
            const int gr0 = bm + wm * 64 + mi * 16 + g;
            const int gr1 = gr0 + 8;
            const int b0v = gr0 >> 11, t0v = gr0 & (T_SZ - 1);
            const int b1v = gr1 >> 11, t1v = gr1 & (T_SZ - 1);
#pragma unroll
            for (int ni = 0; ni < 4; ni++) {
                const int d = wn * 32 + ni * 8 + 2 * t;
                size_t base0 = (((size_t)b0v * NKV + kvh) * HD + d) * T_SZ + t0v;
                size_t base1 = (((size_t)b1v * NKV + kvh) * HD + d) * T_SZ + t1v;
                vt[base0]        = __float2half_rn(acc[mi][ni][0]);
                vt[base0 + T_SZ] = __float2half_rn(acc[mi][ni][1]);
                vt[base1]        = __float2half_rn(acc[mi][ni][2]);
                vt[base1 + T_SZ] = __float2half_rn(acc[mi][ni][3]);
            }
        }
    } else {
        // MODE 1: fused RoPE + RMSNorm -> half (N-tile == one head of 128 dims)
        __syncthreads();
        float* sE = (float*)gsm;            // [128][130]
#pragma unroll
        for (int mi = 0; mi < 4; mi++) {
            const int r = wm * 64 + mi * 16 + g;
#pragma unroll
            for (int ni = 0; ni < 4; ni++) {
                const int c = wn * 32 + ni * 8 + 2 * t;
                *(float2*)&sE[r * SE_LD + c] = make_float2(acc[mi][ni][0], acc[mi][ni][1]);
                *(float2*)&sE[(r + 8) * SE_LD + c] = make_float2(acc[mi][ni][2], acc[mi][ni][3]);
            }
        }
        __syncthreads();

        __half* Ch = (__half*)Cv;
        const int row = tid >> 1;
        const int hf  = tid & 1;
        const int d0  = hf * 64;
        const int gr  = bm + row;
        const int tt  = gr & (T_SZ - 1);
        const float sgn = hf ? 1.f : -1.f;

        float rv[64];
        float ss = 0.f;
        const float* erow = sE + row * SE_LD;
        const float* cr = cosb + (size_t)tt * HD + d0;
        const float* sr = sinb + (size_t)tt * HD + d0;
#pragma unroll
        for (int i = 0; i < 64; i += 2) {
            float2 v = *(const float2*)&erow[d0 + i];
            float2 p = *(const float2*)&erow[(d0 ^ 64) + i];
            float2 c2 = *(const float2*)&cr[i];
            float2 s2 = *(const float2*)&sr[i];
            float r0 = v.x * c2.x + sgn * p.x * s2.x;
            float r1 = v.y * c2.y + sgn * p.y * s2.y;
            rv[i] = r0; rv[i + 1] = r1;
            ss += r0 * r0 + r1 * r1;
        }
        ss += __shfl_xor_sync(0xffffffffu, ss, 1);
        const float inv = rsqrtf(ss * (1.0f / HD) + RMS_EPS);

        __half2* dst = (__half2*)(Ch + (size_t)gr * N + bn + d0);
#pragma unroll
        for (int i = 0; i < 64; i += 2) {
            dst[i >> 1] = __floats2half2_rn(rv[i] * inv, rv[i + 1] * inv);
        }
    }
}

// ---------------- flash attention: fp16 mma + ldmatrix + 3-stage cp.async ----------
#define BM 128
#define BN 64
#define AK_LD 68    // words/row sK: ldmatrix banks 4r+c, conflict-free
#define AV_LD 36    // words/row sVt
#define AK_TILE (BN * AK_LD)
#define AV_TILE (HD * AV_LD)
#define NSTG 3

__global__ __launch_bounds__(256, 1) void attn_f16(const __half* __restrict__ qb,
                                                   const __half* __restrict__ kb,
                                                   const __half* __restrict__ vtb,
                                                   float* __restrict__ yb) {
    extern __shared__ uint32_t smu[];
    uint32_t* sK  = smu;                       // [3][64][68]
    uint32_t* sVt = smu + NSTG * AK_TILE;      // [3][128][36]
    const uint32_t kS = smem_u32(sK);
    const uint32_t vS = smem_u32(sVt);

    const int qt = gridDim.x - 1 - blockIdx.x;   // heavy tiles first
    const int h  = blockIdx.y;
    const int b  = blockIdx.z;
    const int kvh = h >> 2;
    const int qs = qt * BM;
    const int tid  = threadIdx.x;
    const int w    = tid >> 5;
    const int lane = tid & 31;
    const int g    = lane >> 2;
    const int t    = lane & 3;
    const int w16  = w * 16;
    const int lrow8 = lane & 7;
    const int lcolB = ((lane >> 3) & 1) * 4;

    // ---- Q fragments (half2 words straight from global) ----
    uint32_t qa[8][4];
    {
        const uint32_t* q0 = (const uint32_t*)(qb + (size_t)(b * T_SZ + qs + w16 + g) * (NH * HD) + h * HD);
        const uint32_t* q1 = q0 + 8 * (NH * HD / 2);
#pragma unroll
        for (int s16 = 0; s16 < 8; s16++) {
            qa[s16][0] = q0[s16 * 8 + t];
            qa[s16][1] = q1[s16 * 8 + t];
            qa[s16][2] = q0[s16 * 8 + t + 4];
            qa[s16][3] = q1[s16 * 8 + t + 4];
        }
    }

    float m0 = NEG_BIG, m1 = NEG_BIG, l0 = 0.f, l1 = 0.f;
    float o[16][4];
#pragma unroll
    for (int dt = 0; dt < 16; dt++)
#pragma unroll
        for (int r = 0; r < 4; r++) o[dt][r] = 0.f;

    const int row0 = qs + w16 + g;
    const int row1 = row0 + 8;

    // staging indices
    const int kr = tid >> 2, kq = tid & 3;        // K: row 0..63, quarter (64B)
    const int vr = tid >> 1, vh = tid & 1;        // Vt: row 0..127, half (64B)
    const __half* kbase = kb + (size_t)b * T_SZ * (NKV * HD) + kvh * HD;
    const __half* vbase = vtb + (((size_t)b * NKV + kvh) * HD + vr) * T_SZ;

    auto stage_kv = [&](int buf, int ks) {
        uint32_t kd = smem_u32(sK + buf * AK_TILE + kr * AK_LD + kq * 16);
        const __half* ksrc = kbase + (size_t)(ks + kr) * (NKV * HD) + kq * 32;
#pragma unroll
        for (int i = 0; i < 4; i++) CP_ASYNC16(kd + 16 * i, ksrc + 8 * i);
        uint32_t vd = smem_u32(sVt + buf * AV_TILE + vr * AV_LD + vh * 16);
        const __half* vsrc = vbase + ks + vh * 32;
#pragma unroll
        for (int i = 0; i < 4; i++) CP_ASYNC16(vd + 16 * i, vsrc + 8 * i);
    };

    const int ntile = (qs + BM) / BN;
    stage_kv(0, 0);
    CP_COMMIT();
    if (ntile > 1) {
        stage_kv(1, BN);
        CP_COMMIT();
    }

    for (int it = 0; it < ntile; it++) {
        const int buf = it % NSTG;
        const int ks = it * BN;
        if (it + 1 < ntile) { CP_WAIT(1); } else { CP_WAIT(0); }
        __syncthreads();
        if (it + 2 < ntile) {
            stage_kv((it + 2) % NSTG, (it + 2) * BN);
            CP_COMMIT();
        }

        const int lim = qs + w16 + 15 - ks;     // max valid local col for this warp
        if (lim < 0) continue;                   // fully masked for this warp
        const int ntmax = lim >= 63 ? 8 : ((lim >> 3) + 1);
        const int jmax  = lim >= 63 ? 4 : ((lim >> 4) + 1);

        const uint32_t kbuf = kS + 4 * (buf * AK_TILE);
        const uint32_t vbuf = vS + 4 * (buf * AV_TILE);

        // ---- S = Q K^T ----
        float s[8][4];
#pragma unroll
        for (int nb = 0; nb < 8; nb++)
#pragma unroll
            for (int r = 0; r < 4; r++) s[nb][r] = 0.f;

#pragma unroll
        for (int s16 = 0; s16 < 8; s16++) {
#pragma unroll
            for (int nb = 0; nb < 8; nb++) {
                if (nb < ntmax) {
                    uint32_t bf[2];
                    ldsm_x2(bf, kbuf + 4 * ((nb * 8 + lrow8) * AK_LD + s16 * 8 + lcolB));
                    mma_f16(s[nb], qa[s16], bf);
                }
            }
        }

        // ---- online softmax ----
        const bool needs_mask = (ks + BN - 1) > (qs + w16);
        float rm0 = NEG_BIG, rm1 = NEG_BIG;
#pragma unroll
        for (int nb = 0; nb < 8; nb++) {
#pragma unroll
            for (int ci = 0; ci < 2; ci++) {
                const int col = ks + nb * 8 + 2 * t + ci;
                float v0 = s[nb][ci] * ATT_SCALE;
                float v1 = s[nb][2 + ci] * ATT_SCALE;
                if (needs_mask) {
                    if (col > row0) v0 = NEG_BIG;
                    if (col > row1) v1 = NEG_BIG;
                }
                s[nb][ci] = v0;
                s[nb][2 + ci] = v1;
                rm0 = fmaxf(rm0, v0);
                rm1 = fmaxf(rm1, v1);
            }
        }
        rm0 = fmaxf(rm0, __shfl_xor_sync(0xffffffffu, rm0, 1));
        rm0 = fmaxf(rm0, __shfl_xor_sync(0xffffffffu, rm0, 2));
        rm1 = fmaxf(rm1, __shfl_xor_sync(0xffffffffu, rm1, 1));
        rm1 = fmaxf(rm1, __shfl_xor_sync(0xffffffffu, rm1, 2));

        const float mn0 = fmaxf(m0, rm0);
        const float mn1 = fmaxf(m1, rm1);
        const float corr0 = __expf(m0 - mn0);
        const float corr1 = __expf(m1 - mn1);
        m0 = mn0; m1 = mn1;

        float rs0 = 0.f, rs1 = 0.f;
#pragma unroll
        for (int nb = 0; nb < 8; nb++) {
#pragma unroll
            for (int ci = 0; ci < 2; ci++) {
                float p0 = __expf(s[nb][ci] - mn0);
                float p1 = __expf(s[nb][2 + ci] - mn1);
                s[nb][ci] = p0;
                s[nb][2 + ci] = p1;
                rs0 += p0;
                rs1 += p1;
            }
        }
        rs0 += __shfl_xor_sync(0xffffffffu, rs0, 1);
        rs0 += __shfl_xor_sync(0xffffffffu, rs0, 2);
        rs1 += __shfl_xor_sync(0xffffffffu, rs1, 1);
        rs1 += __shfl_xor_sync(0xffffffffu, rs1, 2);

        l0 = l0 * corr0 + rs0;
        l1 = l1 * corr1 + rs1;

#pragma unroll
        for (int dt = 0; dt < 16; dt++) {
            o[dt][0] *= corr0; o[dt][1] *= corr0;
            o[dt][2] *= corr1; o[dt][3] *= corr1;
        }

        // ---- O += P V : accumulator -> half2 A-frags directly ----
#pragma unroll
        for (int j = 0; j < 4; j++) {
            if (j < jmax) {
                uint32_t pa[4];
                pa[0] = packh2(s[2 * j][0], s[2 * j][1]);
                pa[1] = packh2(s[2 * j][2], s[2 * j][3]);
                pa[2] = packh2(s[2 * j + 1][0], s[2 * j + 1][1]);
                pa[3] = packh2(s[2 * j + 1][2], s[2 * j + 1][3]);
#pragma unroll
                for (int dt = 0; dt < 16; dt++) {
                    uint32_t bf[2];
                    ldsm_x2(bf, vbuf + 4 * ((dt * 8 + lrow8) * AV_LD + j * 8 + lcolB));
                    mma_f16(o[dt], pa, bf);
                }
            }
        }
    }

    // ---- epilogue (fp32 out) ----
    const float inv0 = 1.0f / l0;
    const float inv1 = 1.0f / l1;
    float* dst0 = yb + (size_t)(b * T_SZ + row0) * C_SZ + h * HD;
    float* dst1 = yb + (size_t)(b * T_SZ + row1) * C_SZ + h * HD;
#pragma unroll
    for (int dt = 0; dt < 16; dt++) {
        *(float2*)&dst0[dt * 8 + 2 * t] = make_float2(o[dt][0] * inv0, o[dt][1] * inv0);
        *(float2*)&dst1[dt * 8 + 2 * t] = make_float2(o[dt][2] * inv1, o[dt][3] * inv1);
    }
}

// ---------------- launch ---------------------------------------------------------
extern "C" void kernel_launch(void* const* d_in, const int* in_sizes, int n_in,
                              void* d_out, int out_size) {
    const float* x     = (const float*)d_in[0];
    const float* cosb  = (const float*)d_in[1];
    const float* sinb  = (const float*)d_in[2];
    const float* wq    = (const float*)d_in[3];
    const float* wk    = (const float*)d_in[4];
    const float* wv    = (const float*)d_in[5];
    const float* wproj = (const float*)d_in[6];
    float* out = (float*)d_out;

    __half *qp, *kp, *vtp;
    float *yp;
    cudaGetSymbolAddress((void**)&qp,  g_q);
    cudaGetSymbolAddress((void**)&kp,  g_k);
    cudaGetSymbolAddress((void**)&vtp, g_vt);
    cudaGetSymbolAddress((void**)&yp,  g_y);

    const int M = B_SZ * T_SZ;   // 4096

    const int smem_plain = 4 * GTILEW * sizeof(uint32_t);           // 40960
    const int smem_rope  = 128 * SE_LD * sizeof(float);             // 66560
    cudaFuncSetAttribute(gemm_f16<0>, cudaFuncAttributeMaxDynamicSharedMemorySize, smem_plain);
    cudaFuncSetAttribute(gemm_f16<1>, cudaFuncAttributeMaxDynamicSharedMemorySize, smem_rope);
    cudaFuncSetAttribute(gemm_f16<2>, cudaFuncAttributeMaxDynamicSharedMemorySize, smem_plain);

    // QKV projections: q/k fused RoPE+RMSNorm -> half; v -> transposed half
    gemm_f16<1><<<dim3((NH * HD) / 128, M / 128), 256, smem_rope>>>(
        x, wq, (void*)qp, M, NH * HD, C_SZ, cosb, sinb);
    gemm_f16<1><<<dim3((NKV * HD) / 128, M / 128), 256, smem_rope>>>(
        x, wk, (void*)kp, M, NKV * HD, C_SZ, cosb, sinb);
    gemm_f16<2><<<dim3((NKV * HD) / 128, M / 128), 256, smem_plain>>>(
        x, wv, (void*)vtp, M, NKV * HD, C_SZ, nullptr, nullptr);

    // attention (3-stage cp.async, ldmatrix)
    const int attn_smem = NSTG * (AK_TILE + AV_TILE) * sizeof(uint32_t);  // 107520
    cudaFuncSetAttribute(attn_f16, cudaFuncAttributeMaxDynamicSharedMemorySize, attn_smem);
    attn_f16<<<dim3(T_SZ / BM, NH, B_SZ), 256, attn_smem>>>(qp, kp, vtp, yp);

    // output projection (fp32 out)
    gemm_f16<0><<<dim3(C_SZ / 128, M / 128), 256, smem_plain>>>(
        yp, wproj, (void*)out, M, C_SZ, C_SZ, nullptr, nullptr);
}